// round 13
// baseline (speedup 1.0000x reference)
#include <cuda_runtime.h>
#include <cuda_fp16.h>
#include <cstdint>

#define BATCH 8
#define NPTS  4096
#define MPTS  4096
#define CDIM  128
#define TILE  128
#define STRIP 8          // B tiles per CTA (along columns)
#define INF_BITS 0x7F800000u

// ---------------- device scratch (no allocation allowed) -------------------
__device__ unsigned  g_rowmin[BATCH * NPTS];
__device__ unsigned  g_colmin[BATCH * MPTS];
__device__ float     g_norm1[BATCH * NPTS];
__device__ float     g_norm2[BATCH * MPTS];
__device__ __half    g_h1[BATCH * NPTS * CDIM];   // holds -2*x_hat (fp16)
__device__ __half    g_h2[BATCH * MPTS * CDIM];   // holds  y_hat  (fp16)
__device__ float     g_partial[256];
__device__ unsigned  g_done;

// ---------------- PTX helpers (plain sm_80+ instructions only) -------------
__device__ __forceinline__ uint32_t smem_u32(const void* p) {
    uint32_t a;
    asm("{ .reg .u64 t; cvta.to.shared.u64 t, %1; cvt.u32.u64 %0, t; }" : "=r"(a) : "l"(p));
    return a;
}
__device__ __forceinline__ void ldmatrix_x4(uint32_t& r0, uint32_t& r1,
                                            uint32_t& r2, uint32_t& r3, uint32_t addr) {
    asm volatile("ldmatrix.sync.aligned.m8n8.x4.shared.b16 {%0,%1,%2,%3}, [%4];"
                 : "=r"(r0), "=r"(r1), "=r"(r2), "=r"(r3) : "r"(addr));
}
// fp16 inputs, fp16 accumulators (2 regs)
__device__ __forceinline__ void mma16816_f16(uint32_t* d, const uint32_t* a,
                                             uint32_t b0, uint32_t b1) {
    asm volatile("mma.sync.aligned.m16n8k16.row.col.f16.f16.f16.f16 "
                 "{%0,%1}, {%2,%3,%4,%5}, {%6,%7}, {%0,%1};"
                 : "+r"(d[0]), "+r"(d[1])
                 : "r"(a[0]), "r"(a[1]), "r"(a[2]), "r"(a[3]), "r"(b0), "r"(b1));
}
__device__ __forceinline__ void lds128(uint32_t* r, uint32_t addr) {
    asm volatile("ld.shared.v4.u32 {%0,%1,%2,%3}, [%4];"
                 : "=r"(r[0]), "=r"(r[1]), "=r"(r[2]), "=r"(r[3]) : "r"(addr));
}
__device__ __forceinline__ uint32_t hfma2u(uint32_t a, uint32_t b, uint32_t c) {
    __half2 r = __hfma2(*reinterpret_cast<__half2*>(&a),
                        *reinterpret_cast<__half2*>(&b),
                        *reinterpret_cast<__half2*>(&c));
    return *reinterpret_cast<uint32_t*>(&r);
}
#define CP_ASYNC16(dst, src) \
    asm volatile("cp.async.cg.shared.global [%0], [%1], 16;" :: "r"(dst), "l"(src))
#define CP_COMMIT() asm volatile("cp.async.commit_group;" ::: "memory")
#define CP_WAIT0()  asm volatile("cp.async.wait_group 0;" ::: "memory")

// ---------------- kernel 1: fused convert(fp16) + norm + min-init -----------
__global__ void prep_kernel(const float* __restrict__ s1, const float* __restrict__ s2) {
    if (blockIdx.x == 0 && threadIdx.x == 0) g_done = 0;
    const int total1 = BATCH * NPTS;
    int row = blockIdx.x * 32 + (threadIdx.x >> 3);
    int sub = threadIdx.x & 7;
    bool isA = row < total1;
    const float* src;
    __half* dst;
    int j;
    if (isA) { src = s1; dst = g_h1; j = row; }
    else     { src = s2; dst = g_h2; j = row - total1; }
    const float mul = isA ? -2.0f : 1.0f;
    const float* rp = src + (size_t)j * CDIM + sub * 16;
    __half* wp = dst + (size_t)j * CDIM + sub * 16;

    float s = 0.f;
#pragma unroll
    for (int h = 0; h < 2; h++) {
        float4 a = *reinterpret_cast<const float4*>(rp + h * 8);
        float4 b = *reinterpret_cast<const float4*>(rp + h * 8 + 4);
        __half2 p0 = __floats2half2_rn(mul * a.x, mul * a.y);
        __half2 p1 = __floats2half2_rn(mul * a.z, mul * a.w);
        __half2 p2 = __floats2half2_rn(mul * b.x, mul * b.y);
        __half2 p3 = __floats2half2_rn(mul * b.z, mul * b.w);
        uint4 o;
        o.x = *reinterpret_cast<unsigned*>(&p0);
        o.y = *reinterpret_cast<unsigned*>(&p1);
        o.z = *reinterpret_cast<unsigned*>(&p2);
        o.w = *reinterpret_cast<unsigned*>(&p3);
        *reinterpret_cast<uint4*>(wp + h * 8) = o;
        float2 f0 = __half22float2(p0);
        float2 f1 = __half22float2(p1);
        float2 f2 = __half22float2(p2);
        float2 f3 = __half22float2(p3);
        s += f0.x * f0.x + f0.y * f0.y + f1.x * f1.x + f1.y * f1.y;
        s += f2.x * f2.x + f2.y * f2.y + f3.x * f3.x + f3.y * f3.y;
    }
    s += __shfl_down_sync(0xffffffffu, s, 4, 8);
    s += __shfl_down_sync(0xffffffffu, s, 2, 8);
    s += __shfl_down_sync(0xffffffffu, s, 1, 8);
    if (sub == 0) {
        if (isA) { g_norm1[j] = 0.25f * s; g_rowmin[j] = INF_BITS; }
        else     { g_norm2[j] = s;         g_colmin[j] = INF_BITS; }
    }
}

// ---------------- kernel 2: hybrid tensor(rows 0-111) + HFMA2(rows 112-127) -
static constexpr int SMEM_A_OFF  = 0;
static constexpr int SMEM_B0_OFF = 32768;
static constexpr int SMEM_B1_OFF = 65536;
static constexpr int SMEM_N1     = 98304;
static constexpr int SMEM_N2     = 98816;
static constexpr int SMEM_RMIN   = 99328;
static constexpr int SMEM_CMIN   = 99840;
static constexpr int SMEM_TOTAL  = 100352;

__global__ __launch_bounds__(256, 2)
void chamfer_mma() {
    extern __shared__ char smem[];
    const uint32_t sb = smem_u32(smem);
    const int tid  = threadIdx.x;
    const int wid  = tid >> 5;
    const int lane = tid & 31;
    const int wr   = wid >> 2;        // 0: rows 0-63 (4 mi); 1: rows 64-111 (3 mi)
    const int wc   = wid & 3;
    const bool full = (wr == 0);      // warp-uniform: does mi==3 exist
    const int brow  = blockIdx.y * TILE;
    const int bcol0 = blockIdx.x * (TILE * STRIP);
    const int b     = blockIdx.z;

    float*    n1s    = reinterpret_cast<float*>(smem + SMEM_N1);
    float*    n2s    = reinterpret_cast<float*>(smem + SMEM_N2);
    unsigned* rmin_s = reinterpret_cast<unsigned*>(smem + SMEM_RMIN);
    unsigned* cmin_s = reinterpret_cast<unsigned*>(smem + SMEM_CMIN);

    const __half* Ag  = g_h1 + ((size_t)b * NPTS + brow) * CDIM;
    const __half* Bg0 = g_h2 + ((size_t)b * MPTS + bcol0) * CDIM;

    // ---- prologue: async-load A tile + B tile 0 ----
#pragma unroll
    for (int p = 0; p < 8; p++) {
        int c = p * 256 + tid;
        int row = c >> 4, col16 = c & 15;
        uint32_t so = row * 256 + ((col16 ^ (row & 7)) << 4);
        CP_ASYNC16(sb + SMEM_A_OFF + so,  Ag  + row * CDIM + col16 * 8);
    }
#pragma unroll
    for (int p = 0; p < 8; p++) {
        int c = p * 256 + tid;
        int row = c >> 4, col16 = c & 15;
        uint32_t so = row * 256 + ((col16 ^ (row & 7)) << 4);
        CP_ASYNC16(sb + SMEM_B0_OFF + so, Bg0 + row * CDIM + col16 * 8);
    }
    CP_COMMIT();
    if (tid < TILE) {
        n1s[tid] = g_norm1[b * NPTS + brow + tid];
        rmin_s[tid] = INF_BITS;
    }

    // thread geometry
    const int m  = lane >> 3;
    const int li = lane & 7;
    const int ksel = m >> 1;
    const int q = lane >> 2;
    const int s = lane & 3;
    const float INF = __uint_as_float(INF_BITS);

    // scalar-path geometry: rows 112-127, cols 4*cg..4*cg+3
    const int sv  = tid & 7;          // row sub-index
    const int cg  = tid >> 3;         // 0..31
    const int sr0 = 112 + sv;
    const int sr1 = 120 + sv;
    const uint32_t aS0 = sb + SMEM_A_OFF + sr0 * 256;   // + ((oct ^ (sr0&7))<<4)
    const uint32_t aS1 = sb + SMEM_A_OFF + sr1 * 256;

    uint32_t a_base[4];
#pragma unroll
    for (int mi = 0; mi < 4; mi++)
        a_base[mi] = sb + SMEM_A_OFF + (wr * 64 + mi * 16 + (m & 1) * 8 + li) * 256;

    float n1r[4][2];
    float rowm[4][2];
#pragma unroll
    for (int mi = 0; mi < 4; mi++) { rowm[mi][0] = INF; rowm[mi][1] = INF; }
    float srowm0 = INF, srowm1 = INF;
    float sn1_0 = 0.f, sn1_1 = 0.f;

    for (int it = 0; it < STRIP; it++) {
        CP_WAIT0();
        __syncthreads();

        if (it + 1 < STRIP) {
            const __half* Bn = Bg0 + (size_t)(it + 1) * TILE * CDIM;
            uint32_t dstb = sb + ((it + 1) & 1 ? SMEM_B1_OFF : SMEM_B0_OFF);
#pragma unroll
            for (int p = 0; p < 8; p++) {
                int c = p * 256 + tid;
                int row = c >> 4, col16 = c & 15;
                uint32_t so = row * 256 + ((col16 ^ (row & 7)) << 4);
                CP_ASYNC16(dstb + so, Bn + row * CDIM + col16 * 8);
            }
            CP_COMMIT();
        }
        if (tid < TILE) {
            n2s[tid] = g_norm2[b * MPTS + bcol0 + it * TILE + tid];
            cmin_s[tid] = INF_BITS;
        }
        if (it == 0) {
#pragma unroll
            for (int mi = 0; mi < 4; mi++) {
                n1r[mi][0] = n1s[wr * 64 + mi * 16 + q];
                n1r[mi][1] = n1s[wr * 64 + mi * 16 + q + 8];
            }
            sn1_0 = n1s[sr0];
            sn1_1 = n1s[sr1];
        }

        // ---- mainloop (tensor rows 0-111 + scalar rows 112-127) ----
        const uint32_t sbB = sb + ((it & 1) ? SMEM_B1_OFF : SMEM_B0_OFF);
        uint32_t b_base[2];
#pragma unroll
        for (int nj2 = 0; nj2 < 2; nj2++)
            b_base[nj2] = sbB + (wc * 32 + nj2 * 16 + (m & 1) * 8 + li) * 256;

        uint32_t acc[4][4][2];
#pragma unroll
        for (int mi = 0; mi < 4; mi++)
#pragma unroll
            for (int nj = 0; nj < 4; nj++) { acc[mi][nj][0] = 0u; acc[mi][nj][1] = 0u; }
        uint32_t sacc0[4] = {0u, 0u, 0u, 0u};
        uint32_t sacc1[4] = {0u, 0u, 0u, 0u};

#pragma unroll
        for (int kk = 0; kk < 8; kk++) {
            const uint32_t xoff = (uint32_t)(((kk * 2 + ksel) ^ li) << 4);
            uint32_t af[4][4], bf[2][4];
#pragma unroll
            for (int mi = 0; mi < 3; mi++)
                ldmatrix_x4(af[mi][0], af[mi][1], af[mi][2], af[mi][3], a_base[mi] + xoff);
            if (full)
                ldmatrix_x4(af[3][0], af[3][1], af[3][2], af[3][3], a_base[3] + xoff);
#pragma unroll
            for (int nj2 = 0; nj2 < 2; nj2++)
                ldmatrix_x4(bf[nj2][0], bf[nj2][1], bf[nj2][2], bf[nj2][3], b_base[nj2] + xoff);
#pragma unroll
            for (int mi = 0; mi < 4; mi++) {
                if (mi < 3 || full) {
#pragma unroll
                    for (int nj = 0; nj < 4; nj++)
                        mma16816_f16(acc[mi][nj], af[mi], bf[nj >> 1][nj & 1], bf[nj >> 1][2 + (nj & 1)]);
                }
            }
            // scalar: 2 k-octets per kk, overlaps on FMA pipe
#pragma unroll
            for (int oc = 0; oc < 2; oc++) {
                const int oct = kk * 2 + oc;
                uint32_t a0[4], a1[4];
                lds128(a0, aS0 + (uint32_t)((oct ^ (sr0 & 7)) << 4));
                lds128(a1, aS1 + (uint32_t)((oct ^ (sr1 & 7)) << 4));
#pragma unroll
                for (int cc = 0; cc < 4; cc++) {
                    const int c = 4 * cg + cc;
                    uint32_t bq[4];
                    lds128(bq, sbB + (uint32_t)(c * 256 + ((oct ^ (c & 7)) << 4)));
#pragma unroll
                    for (int i = 0; i < 4; i++) {
                        sacc0[cc] = hfma2u(a0[i], bq[i], sacc0[cc]);
                        sacc1[cc] = hfma2u(a1[i], bq[i], sacc1[cc]);
                    }
                }
            }
        }
        __syncthreads();   // mainloop done; n2s/cmin ready

        // ---- tensor epilogue (rows 0-111) ----
        float n2c[4][2];
#pragma unroll
        for (int nj = 0; nj < 4; nj++) {
            n2c[nj][0] = n2s[wc * 32 + nj * 8 + 2 * s];
            n2c[nj][1] = n2s[wc * 32 + nj * 8 + 2 * s + 1];
        }
        float colm[4][2];
#pragma unroll
        for (int nj = 0; nj < 4; nj++) { colm[nj][0] = INF; colm[nj][1] = INF; }

#pragma unroll
        for (int mi = 0; mi < 4; mi++) {
            if (mi < 3 || full) {
#pragma unroll
                for (int nj = 0; nj < 4; nj++) {
                    float2 lo = __half22float2(*reinterpret_cast<__half2*>(&acc[mi][nj][0]));
                    float2 hi = __half22float2(*reinterpret_cast<__half2*>(&acc[mi][nj][1]));
                    rowm[mi][0] = fminf(rowm[mi][0], lo.x + n2c[nj][0]);
                    rowm[mi][0] = fminf(rowm[mi][0], lo.y + n2c[nj][1]);
                    rowm[mi][1] = fminf(rowm[mi][1], hi.x + n2c[nj][0]);
                    rowm[mi][1] = fminf(rowm[mi][1], hi.y + n2c[nj][1]);
                    colm[nj][0] = fminf(colm[nj][0], lo.x + n1r[mi][0]);
                    colm[nj][1] = fminf(colm[nj][1], lo.y + n1r[mi][0]);
                    colm[nj][0] = fminf(colm[nj][0], hi.x + n1r[mi][1]);
                    colm[nj][1] = fminf(colm[nj][1], hi.y + n1r[mi][1]);
                }
            }
        }
#pragma unroll
        for (int nj = 0; nj < 4; nj++) {
#pragma unroll
            for (int h = 0; h < 2; h++) {
                float v = colm[nj][h];
                v = fminf(v, __shfl_xor_sync(0xffffffffu, v, 4));
                v = fminf(v, __shfl_xor_sync(0xffffffffu, v, 8));
                v = fminf(v, __shfl_xor_sync(0xffffffffu, v, 16));
                if (q == 0) {
                    float d2 = fmaxf(v + n2c[nj][h], 0.0f);
                    atomicMin(&cmin_s[wc * 32 + nj * 8 + 2 * s + h], __float_as_uint(d2));
                }
            }
        }
        // ---- scalar epilogue (rows 112-127) ----
#pragma unroll
        for (int cc = 0; cc < 4; cc++) {
            const int c = 4 * cg + cc;
            float2 f0 = __half22float2(*reinterpret_cast<__half2*>(&sacc0[cc]));
            float2 f1 = __half22float2(*reinterpret_cast<__half2*>(&sacc1[cc]));
            float t0 = f0.x + f0.y;
            float t1 = f1.x + f1.y;
            srowm0 = fminf(srowm0, t0 + n2s[c]);
            srowm1 = fminf(srowm1, t1 + n2s[c]);
            float v = fminf(t0 + sn1_0, t1 + sn1_1);
            v = fminf(v, __shfl_xor_sync(0xffffffffu, v, 1));
            v = fminf(v, __shfl_xor_sync(0xffffffffu, v, 2));
            v = fminf(v, __shfl_xor_sync(0xffffffffu, v, 4));
            if (sv == 0) {
                float d2 = fmaxf(v + n2s[c], 0.0f);
                atomicMin(&cmin_s[c], __float_as_uint(d2));
            }
        }
        __syncthreads();
        if (tid < TILE)
            atomicMin(&g_colmin[b * MPTS + bcol0 + it * TILE + tid], cmin_s[tid]);
    }

    // ---- strip end: tensor row mins ----
#pragma unroll
    for (int mi = 0; mi < 4; mi++) {
#pragma unroll
        for (int h = 0; h < 2; h++) {
            float v = rowm[mi][h];     // stays INF for wr1 mi==3 (never folded)
            v = fminf(v, __shfl_xor_sync(0xffffffffu, v, 1));
            v = fminf(v, __shfl_xor_sync(0xffffffffu, v, 2));
            if (s == 0 && (mi < 3 || full)) {
                float d2 = fmaxf(v + n1r[mi][h], 0.0f);
                atomicMin(&rmin_s[wr * 64 + mi * 16 + q + h * 8], __float_as_uint(d2));
            }
        }
    }
    // ---- strip end: scalar row mins (rows 112-127) ----
    {
        float d0 = srowm0 + sn1_0;
        float d1 = srowm1 + sn1_1;
        d0 = fminf(d0, __shfl_xor_sync(0xffffffffu, d0, 8));
        d0 = fminf(d0, __shfl_xor_sync(0xffffffffu, d0, 16));
        d1 = fminf(d1, __shfl_xor_sync(0xffffffffu, d1, 8));
        d1 = fminf(d1, __shfl_xor_sync(0xffffffffu, d1, 16));
        if (lane < 8) {
            atomicMin(&rmin_s[112 + sv], __float_as_uint(fmaxf(d0, 0.0f)));
            atomicMin(&rmin_s[120 + sv], __float_as_uint(fmaxf(d1, 0.0f)));
        }
    }
    __syncthreads();
    if (tid < TILE)
        atomicMin(&g_rowmin[b * NPTS + brow + tid], rmin_s[tid]);
}

// ---------------- kernel 3: fused deterministic weighted reduction ----------
__global__ void reduce_all(const float* __restrict__ w1,
                           const float* __restrict__ w2,
                           float* __restrict__ out) {
    __shared__ float red[256];
    __shared__ unsigned slast;
    const int t = threadIdx.x;
    const int bid = blockIdx.x;            // 0..255
    const int total1 = BATCH * NPTS;       // 32768
    const int idx = bid * 256 + t;         // 0 .. 65535
    float sum;
    if (idx < total1)
        sum = w1[idx] * sqrtf(__uint_as_float(g_rowmin[idx]));
    else {
        int j = idx - total1;
        sum = w2[j] * sqrtf(__uint_as_float(g_colmin[j]));
    }
    red[t] = sum;
    __syncthreads();
    for (int o = 128; o > 0; o >>= 1) {
        if (t < o) red[t] += red[t + o];
        __syncthreads();
    }
    if (t == 0) {
        g_partial[bid] = red[0];
        __threadfence();
        unsigned prev = atomicAdd(&g_done, 1u);
        slast = (prev == 255u) ? 1u : 0u;
    }
    __syncthreads();
    if (slast) {
        volatile float* gp = g_partial;
        red[t] = gp[t];
        __syncthreads();
        for (int o = 128; o > 0; o >>= 1) {
            if (t < o) red[t] += red[t + o];
            __syncthreads();
        }
        if (t == 0) out[0] = red[0] * 0.5f;
    }
}

// ---------------------------------------------------------------------------
extern "C" void kernel_launch(void* const* d_in, const int* in_sizes, int n_in,
                              void* d_out, int out_size) {
    const float* set1 = (const float*)d_in[0];
    const float* set2 = (const float*)d_in[1];
    const float* w1   = (const float*)d_in[2];
    const float* w2   = (const float*)d_in[3];
    float* out = (float*)d_out;
    (void)in_sizes; (void)n_in; (void)out_size;

    static bool attr_done = false;
    if (!attr_done) {
        cudaFuncSetAttribute(chamfer_mma, cudaFuncAttributeMaxDynamicSharedMemorySize, SMEM_TOTAL);
        attr_done = true;
    }

    prep_kernel<<<2 * BATCH * NPTS / 32, 256>>>(set1, set2);
    dim3 grid(MPTS / (TILE * STRIP), NPTS / TILE, BATCH);
    chamfer_mma<<<grid, 256, SMEM_TOTAL>>>();
    reduce_all<<<256, 256>>>(w1, w2, out);
}

// round 14
// speedup vs baseline: 1.0014x; 1.0014x over previous
#include <cuda_runtime.h>
#include <cuda_fp16.h>
#include <cstdint>

#define BATCH 8
#define NPTS  4096
#define MPTS  4096
#define CDIM  128
#define TILE  128
#define STRIP 8          // B tiles per CTA (along columns)
#define INF_BITS 0x7F800000u

// ---------------- device scratch (no allocation allowed) -------------------
__device__ unsigned  g_rowmin[BATCH * NPTS];
__device__ unsigned  g_colmin[BATCH * MPTS];
__device__ float     g_norm1[BATCH * NPTS];
__device__ float     g_norm2[BATCH * MPTS];
__device__ __half    g_h1[BATCH * NPTS * CDIM];   // holds -2*x_hat (fp16)
__device__ __half    g_h2[BATCH * MPTS * CDIM];   // holds  y_hat  (fp16)
__device__ float     g_partial[256];
__device__ unsigned  g_done;

// ---------------- PTX helpers (plain sm_80+ instructions only) -------------
__device__ __forceinline__ uint32_t smem_u32(const void* p) {
    uint32_t a;
    asm("{ .reg .u64 t; cvta.to.shared.u64 t, %1; cvt.u32.u64 %0, t; }" : "=r"(a) : "l"(p));
    return a;
}
__device__ __forceinline__ void ldmatrix_x4(uint32_t& r0, uint32_t& r1,
                                            uint32_t& r2, uint32_t& r3, uint32_t addr) {
    asm volatile("ldmatrix.sync.aligned.m8n8.x4.shared.b16 {%0,%1,%2,%3}, [%4];"
                 : "=r"(r0), "=r"(r1), "=r"(r2), "=r"(r3) : "r"(addr));
}
// fp16 inputs, fp16 accumulators (2 regs)
__device__ __forceinline__ void mma16816_f16(uint32_t* d, const uint32_t* a,
                                             uint32_t b0, uint32_t b1) {
    asm volatile("mma.sync.aligned.m16n8k16.row.col.f16.f16.f16.f16 "
                 "{%0,%1}, {%2,%3,%4,%5}, {%6,%7}, {%0,%1};"
                 : "+r"(d[0]), "+r"(d[1])
                 : "r"(a[0]), "r"(a[1]), "r"(a[2]), "r"(a[3]), "r"(b0), "r"(b1));
}
__device__ __forceinline__ void lds128(uint32_t* r, uint32_t addr) {
    asm volatile("ld.shared.v4.u32 {%0,%1,%2,%3}, [%4];"
                 : "=r"(r[0]), "=r"(r[1]), "=r"(r[2]), "=r"(r[3]) : "r"(addr));
}
__device__ __forceinline__ uint32_t hfma2u(uint32_t a, uint32_t b, uint32_t c) {
    __half2 r = __hfma2(*reinterpret_cast<__half2*>(&a),
                        *reinterpret_cast<__half2*>(&b),
                        *reinterpret_cast<__half2*>(&c));
    return *reinterpret_cast<uint32_t*>(&r);
}
#define CP_ASYNC16(dst, src) \
    asm volatile("cp.async.cg.shared.global [%0], [%1], 16;" :: "r"(dst), "l"(src))
#define CP_COMMIT() asm volatile("cp.async.commit_group;" ::: "memory")
#define CP_WAIT0()  asm volatile("cp.async.wait_group 0;" ::: "memory")

// ---------------- kernel 1: fused convert(fp16) + norm + min-init -----------
__global__ void prep_kernel(const float* __restrict__ s1, const float* __restrict__ s2) {
    if (blockIdx.x == 0 && threadIdx.x == 0) g_done = 0;
    const int total1 = BATCH * NPTS;
    int row = blockIdx.x * 32 + (threadIdx.x >> 3);
    int sub = threadIdx.x & 7;
    bool isA = row < total1;
    const float* src;
    __half* dst;
    int j;
    if (isA) { src = s1; dst = g_h1; j = row; }
    else     { src = s2; dst = g_h2; j = row - total1; }
    const float mul = isA ? -2.0f : 1.0f;
    const float* rp = src + (size_t)j * CDIM + sub * 16;
    __half* wp = dst + (size_t)j * CDIM + sub * 16;

    float s = 0.f;
#pragma unroll
    for (int h = 0; h < 2; h++) {
        float4 a = *reinterpret_cast<const float4*>(rp + h * 8);
        float4 b = *reinterpret_cast<const float4*>(rp + h * 8 + 4);
        __half2 p0 = __floats2half2_rn(mul * a.x, mul * a.y);
        __half2 p1 = __floats2half2_rn(mul * a.z, mul * a.w);
        __half2 p2 = __floats2half2_rn(mul * b.x, mul * b.y);
        __half2 p3 = __floats2half2_rn(mul * b.z, mul * b.w);
        uint4 o;
        o.x = *reinterpret_cast<unsigned*>(&p0);
        o.y = *reinterpret_cast<unsigned*>(&p1);
        o.z = *reinterpret_cast<unsigned*>(&p2);
        o.w = *reinterpret_cast<unsigned*>(&p3);
        *reinterpret_cast<uint4*>(wp + h * 8) = o;
        float2 f0 = __half22float2(p0);
        float2 f1 = __half22float2(p1);
        float2 f2 = __half22float2(p2);
        float2 f3 = __half22float2(p3);
        s += f0.x * f0.x + f0.y * f0.y + f1.x * f1.x + f1.y * f1.y;
        s += f2.x * f2.x + f2.y * f2.y + f3.x * f3.x + f3.y * f3.y;
    }
    s += __shfl_down_sync(0xffffffffu, s, 4, 8);
    s += __shfl_down_sync(0xffffffffu, s, 2, 8);
    s += __shfl_down_sync(0xffffffffu, s, 1, 8);
    if (sub == 0) {
        if (isA) { g_norm1[j] = 0.25f * s; g_rowmin[j] = INF_BITS; }
        else     { g_norm2[j] = s;         g_colmin[j] = INF_BITS; }
    }
}

// ---------------- kernel 2: hybrid tensor(rows 0-111) + HFMA2(rows 112-127) -
static constexpr int SMEM_A_OFF  = 0;
static constexpr int SMEM_B0_OFF = 32768;
static constexpr int SMEM_B1_OFF = 65536;
static constexpr int SMEM_N1     = 98304;
static constexpr int SMEM_N2     = 98816;
static constexpr int SMEM_RMIN   = 99328;
static constexpr int SMEM_CMIN   = 99840;
static constexpr int SMEM_TOTAL  = 100352;

__global__ __launch_bounds__(256, 2)
void chamfer_mma() {
    extern __shared__ char smem[];
    const uint32_t sb = smem_u32(smem);
    const int tid  = threadIdx.x;
    const int wid  = tid >> 5;
    const int lane = tid & 31;
    const int wr   = wid >> 2;        // 0: rows 0-63 (4 mi); 1: rows 64-111 (3 mi)
    const int wc   = wid & 3;
    const bool full = (wr == 0);      // warp-uniform: does mi==3 exist
    const int brow  = blockIdx.y * TILE;
    const int bcol0 = blockIdx.x * (TILE * STRIP);
    const int b     = blockIdx.z;

    float*    n1s    = reinterpret_cast<float*>(smem + SMEM_N1);
    float*    n2s    = reinterpret_cast<float*>(smem + SMEM_N2);
    unsigned* rmin_s = reinterpret_cast<unsigned*>(smem + SMEM_RMIN);
    unsigned* cmin_s = reinterpret_cast<unsigned*>(smem + SMEM_CMIN);

    const __half* Ag  = g_h1 + ((size_t)b * NPTS + brow) * CDIM;
    const __half* Bg0 = g_h2 + ((size_t)b * MPTS + bcol0) * CDIM;

    // ---- prologue: async-load A tile + B tile 0 ----
#pragma unroll
    for (int p = 0; p < 8; p++) {
        int c = p * 256 + tid;
        int row = c >> 4, col16 = c & 15;
        uint32_t so = row * 256 + ((col16 ^ (row & 7)) << 4);
        CP_ASYNC16(sb + SMEM_A_OFF + so,  Ag  + row * CDIM + col16 * 8);
    }
#pragma unroll
    for (int p = 0; p < 8; p++) {
        int c = p * 256 + tid;
        int row = c >> 4, col16 = c & 15;
        uint32_t so = row * 256 + ((col16 ^ (row & 7)) << 4);
        CP_ASYNC16(sb + SMEM_B0_OFF + so, Bg0 + row * CDIM + col16 * 8);
    }
    CP_COMMIT();
    if (tid < TILE) {
        n1s[tid] = g_norm1[b * NPTS + brow + tid];
        rmin_s[tid] = INF_BITS;
    }

    // thread geometry
    const int m  = lane >> 3;
    const int li = lane & 7;
    const int ksel = m >> 1;
    const int q = lane >> 2;
    const int s = lane & 3;
    const float INF = __uint_as_float(INF_BITS);

    // scalar-path geometry: rows 112-127, cols 4*cg..4*cg+3
    const int sv  = tid & 7;          // row sub-index
    const int cg  = tid >> 3;         // 0..31
    const int sr0 = 112 + sv;
    const int sr1 = 120 + sv;
    const uint32_t aS0 = sb + SMEM_A_OFF + sr0 * 256;   // + ((oct ^ (sr0&7))<<4)
    const uint32_t aS1 = sb + SMEM_A_OFF + sr1 * 256;

    uint32_t a_base[4];
#pragma unroll
    for (int mi = 0; mi < 4; mi++)
        a_base[mi] = sb + SMEM_A_OFF + (wr * 64 + mi * 16 + (m & 1) * 8 + li) * 256;

    float n1r[4][2];
    float rowm[4][2];
#pragma unroll
    for (int mi = 0; mi < 4; mi++) { rowm[mi][0] = INF; rowm[mi][1] = INF; }
    float srowm0 = INF, srowm1 = INF;
    float sn1_0 = 0.f, sn1_1 = 0.f;

    for (int it = 0; it < STRIP; it++) {
        CP_WAIT0();
        __syncthreads();

        if (it + 1 < STRIP) {
            const __half* Bn = Bg0 + (size_t)(it + 1) * TILE * CDIM;
            uint32_t dstb = sb + ((it + 1) & 1 ? SMEM_B1_OFF : SMEM_B0_OFF);
#pragma unroll
            for (int p = 0; p < 8; p++) {
                int c = p * 256 + tid;
                int row = c >> 4, col16 = c & 15;
                uint32_t so = row * 256 + ((col16 ^ (row & 7)) << 4);
                CP_ASYNC16(dstb + so, Bn + row * CDIM + col16 * 8);
            }
            CP_COMMIT();
        }
        if (tid < TILE) {
            n2s[tid] = g_norm2[b * MPTS + bcol0 + it * TILE + tid];
            cmin_s[tid] = INF_BITS;
        }
        if (it == 0) {
#pragma unroll
            for (int mi = 0; mi < 4; mi++) {
                n1r[mi][0] = n1s[wr * 64 + mi * 16 + q];
                n1r[mi][1] = n1s[wr * 64 + mi * 16 + q + 8];
            }
            sn1_0 = n1s[sr0];
            sn1_1 = n1s[sr1];
        }

        // ---- mainloop (tensor rows 0-111 + scalar rows 112-127) ----
        const uint32_t sbB = sb + ((it & 1) ? SMEM_B1_OFF : SMEM_B0_OFF);
        uint32_t b_base[2];
#pragma unroll
        for (int nj2 = 0; nj2 < 2; nj2++)
            b_base[nj2] = sbB + (wc * 32 + nj2 * 16 + (m & 1) * 8 + li) * 256;

        uint32_t acc[4][4][2];
#pragma unroll
        for (int mi = 0; mi < 4; mi++)
#pragma unroll
            for (int nj = 0; nj < 4; nj++) { acc[mi][nj][0] = 0u; acc[mi][nj][1] = 0u; }
        uint32_t sacc0[4] = {0u, 0u, 0u, 0u};
        uint32_t sacc1[4] = {0u, 0u, 0u, 0u};

#pragma unroll
        for (int kk = 0; kk < 8; kk++) {
            const uint32_t xoff = (uint32_t)(((kk * 2 + ksel) ^ li) << 4);
            uint32_t af[4][4], bf[2][4];
#pragma unroll
            for (int mi = 0; mi < 3; mi++)
                ldmatrix_x4(af[mi][0], af[mi][1], af[mi][2], af[mi][3], a_base[mi] + xoff);
            if (full)
                ldmatrix_x4(af[3][0], af[3][1], af[3][2], af[3][3], a_base[3] + xoff);
#pragma unroll
            for (int nj2 = 0; nj2 < 2; nj2++)
                ldmatrix_x4(bf[nj2][0], bf[nj2][1], bf[nj2][2], bf[nj2][3], b_base[nj2] + xoff);
#pragma unroll
            for (int mi = 0; mi < 4; mi++) {
                if (mi < 3 || full) {
#pragma unroll
                    for (int nj = 0; nj < 4; nj++)
                        mma16816_f16(acc[mi][nj], af[mi], bf[nj >> 1][nj & 1], bf[nj >> 1][2 + (nj & 1)]);
                }
            }
            // scalar: 2 k-octets per kk, overlaps on FMA pipe
#pragma unroll
            for (int oc = 0; oc < 2; oc++) {
                const int oct = kk * 2 + oc;
                uint32_t a0[4], a1[4];
                lds128(a0, aS0 + (uint32_t)((oct ^ (sr0 & 7)) << 4));
                lds128(a1, aS1 + (uint32_t)((oct ^ (sr1 & 7)) << 4));
#pragma unroll
                for (int cc = 0; cc < 4; cc++) {
                    const int c = 4 * cg + cc;
                    uint32_t bq[4];
                    lds128(bq, sbB + (uint32_t)(c * 256 + ((oct ^ (c & 7)) << 4)));
#pragma unroll
                    for (int i = 0; i < 4; i++) {
                        sacc0[cc] = hfma2u(a0[i], bq[i], sacc0[cc]);
                        sacc1[cc] = hfma2u(a1[i], bq[i], sacc1[cc]);
                    }
                }
            }
        }
        __syncthreads();   // mainloop done; n2s/cmin ready

        // ---- tensor epilogue (rows 0-111) ----
        float n2c[4][2];
#pragma unroll
        for (int nj = 0; nj < 4; nj++) {
            n2c[nj][0] = n2s[wc * 32 + nj * 8 + 2 * s];
            n2c[nj][1] = n2s[wc * 32 + nj * 8 + 2 * s + 1];
        }
        float colm[4][2];
#pragma unroll
        for (int nj = 0; nj < 4; nj++) { colm[nj][0] = INF; colm[nj][1] = INF; }

#pragma unroll
        for (int mi = 0; mi < 4; mi++) {
            if (mi < 3 || full) {
#pragma unroll
                for (int nj = 0; nj < 4; nj++) {
                    float2 lo = __half22float2(*reinterpret_cast<__half2*>(&acc[mi][nj][0]));
                    float2 hi = __half22float2(*reinterpret_cast<__half2*>(&acc[mi][nj][1]));
                    rowm[mi][0] = fminf(rowm[mi][0], lo.x + n2c[nj][0]);
                    rowm[mi][0] = fminf(rowm[mi][0], lo.y + n2c[nj][1]);
                    rowm[mi][1] = fminf(rowm[mi][1], hi.x + n2c[nj][0]);
                    rowm[mi][1] = fminf(rowm[mi][1], hi.y + n2c[nj][1]);
                    colm[nj][0] = fminf(colm[nj][0], lo.x + n1r[mi][0]);
                    colm[nj][1] = fminf(colm[nj][1], lo.y + n1r[mi][0]);
                    colm[nj][0] = fminf(colm[nj][0], hi.x + n1r[mi][1]);
                    colm[nj][1] = fminf(colm[nj][1], hi.y + n1r[mi][1]);
                }
            }
        }
#pragma unroll
        for (int nj = 0; nj < 4; nj++) {
#pragma unroll
            for (int h = 0; h < 2; h++) {
                float v = colm[nj][h];
                v = fminf(v, __shfl_xor_sync(0xffffffffu, v, 4));
                v = fminf(v, __shfl_xor_sync(0xffffffffu, v, 8));
                v = fminf(v, __shfl_xor_sync(0xffffffffu, v, 16));
                if (q == 0) {
                    float d2 = fmaxf(v + n2c[nj][h], 0.0f);
                    atomicMin(&cmin_s[wc * 32 + nj * 8 + 2 * s + h], __float_as_uint(d2));
                }
            }
        }
        // ---- scalar epilogue (rows 112-127) ----
#pragma unroll
        for (int cc = 0; cc < 4; cc++) {
            const int c = 4 * cg + cc;
            float2 f0 = __half22float2(*reinterpret_cast<__half2*>(&sacc0[cc]));
            float2 f1 = __half22float2(*reinterpret_cast<__half2*>(&sacc1[cc]));
            float t0 = f0.x + f0.y;
            float t1 = f1.x + f1.y;
            srowm0 = fminf(srowm0, t0 + n2s[c]);
            srowm1 = fminf(srowm1, t1 + n2s[c]);
            float v = fminf(t0 + sn1_0, t1 + sn1_1);
            v = fminf(v, __shfl_xor_sync(0xffffffffu, v, 1));
            v = fminf(v, __shfl_xor_sync(0xffffffffu, v, 2));
            v = fminf(v, __shfl_xor_sync(0xffffffffu, v, 4));
            if (sv == 0) {
                float d2 = fmaxf(v + n2s[c], 0.0f);
                atomicMin(&cmin_s[c], __float_as_uint(d2));
            }
        }
        __syncthreads();
        if (tid < TILE)
            atomicMin(&g_colmin[b * MPTS + bcol0 + it * TILE + tid], cmin_s[tid]);
    }

    // ---- strip end: tensor row mins ----
#pragma unroll
    for (int mi = 0; mi < 4; mi++) {
#pragma unroll
        for (int h = 0; h < 2; h++) {
            float v = rowm[mi][h];     // stays INF for wr1 mi==3 (never folded)
            v = fminf(v, __shfl_xor_sync(0xffffffffu, v, 1));
            v = fminf(v, __shfl_xor_sync(0xffffffffu, v, 2));
            if (s == 0 && (mi < 3 || full)) {
                float d2 = fmaxf(v + n1r[mi][h], 0.0f);
                atomicMin(&rmin_s[wr * 64 + mi * 16 + q + h * 8], __float_as_uint(d2));
            }
        }
    }
    // ---- strip end: scalar row mins (rows 112-127) ----
    {
        float d0 = srowm0 + sn1_0;
        float d1 = srowm1 + sn1_1;
        d0 = fminf(d0, __shfl_xor_sync(0xffffffffu, d0, 8));
        d0 = fminf(d0, __shfl_xor_sync(0xffffffffu, d0, 16));
        d1 = fminf(d1, __shfl_xor_sync(0xffffffffu, d1, 8));
        d1 = fminf(d1, __shfl_xor_sync(0xffffffffu, d1, 16));
        if (lane < 8) {
            atomicMin(&rmin_s[112 + sv], __float_as_uint(fmaxf(d0, 0.0f)));
            atomicMin(&rmin_s[120 + sv], __float_as_uint(fmaxf(d1, 0.0f)));
        }
    }
    __syncthreads();
    if (tid < TILE)
        atomicMin(&g_rowmin[b * NPTS + brow + tid], rmin_s[tid]);
}

// ---------------- kernel 3: fused deterministic weighted reduction ----------
__global__ void reduce_all(const float* __restrict__ w1,
                           const float* __restrict__ w2,
                           float* __restrict__ out) {
    __shared__ float red[256];
    __shared__ unsigned slast;
    const int t = threadIdx.x;
    const int bid = blockIdx.x;            // 0..255
    const int total1 = BATCH * NPTS;       // 32768
    const int idx = bid * 256 + t;         // 0 .. 65535
    float sum;
    if (idx < total1)
        sum = w1[idx] * sqrtf(__uint_as_float(g_rowmin[idx]));
    else {
        int j = idx - total1;
        sum = w2[j] * sqrtf(__uint_as_float(g_colmin[j]));
    }
    red[t] = sum;
    __syncthreads();
    for (int o = 128; o > 0; o >>= 1) {
        if (t < o) red[t] += red[t + o];
        __syncthreads();
    }
    if (t == 0) {
        g_partial[bid] = red[0];
        __threadfence();
        unsigned prev = atomicAdd(&g_done, 1u);
        slast = (prev == 255u) ? 1u : 0u;
    }
    __syncthreads();
    if (slast) {
        volatile float* gp = g_partial;
        red[t] = gp[t];
        __syncthreads();
        for (int o = 128; o > 0; o >>= 1) {
            if (t < o) red[t] += red[t + o];
            __syncthreads();
        }
        if (t == 0) out[0] = red[0] * 0.5f;
    }
}

// ---------------------------------------------------------------------------
extern "C" void kernel_launch(void* const* d_in, const int* in_sizes, int n_in,
                              void* d_out, int out_size) {
    const float* set1 = (const float*)d_in[0];
    const float* set2 = (const float*)d_in[1];
    const float* w1   = (const float*)d_in[2];
    const float* w2   = (const float*)d_in[3];
    float* out = (float*)d_out;
    (void)in_sizes; (void)n_in; (void)out_size;

    static bool attr_done = false;
    if (!attr_done) {
        cudaFuncSetAttribute(chamfer_mma, cudaFuncAttributeMaxDynamicSharedMemorySize, SMEM_TOTAL);
        attr_done = true;
    }

    prep_kernel<<<2 * BATCH * NPTS / 32, 256>>>(set1, set2);
    dim3 grid(MPTS / (TILE * STRIP), NPTS / TILE, BATCH);
    chamfer_mma<<<grid, 256, SMEM_TOTAL>>>();
    reduce_all<<<256, 256>>>(w1, w2, out);
}

// round 15
// speedup vs baseline: 1.6830x; 1.6807x over previous
#include <cuda_runtime.h>
#include <cuda_fp16.h>
#include <cstdint>

#define BATCH 8
#define NPTS  4096
#define MPTS  4096
#define CDIM  128
#define TILE  128
#define STRIP 8          // B tiles per CTA (along columns)
#define INF_BITS 0x7F800000u

// ---------------- device scratch (no allocation allowed) -------------------
__device__ unsigned  g_rowmin[BATCH * NPTS];
__device__ unsigned  g_colmin[BATCH * MPTS];
__device__ float     g_norm1[BATCH * NPTS];
__device__ float     g_norm2[BATCH * MPTS];
__device__ __half    g_h1[BATCH * NPTS * CDIM];   // holds -2*x_hat (fp16)
__device__ __half    g_h2[BATCH * MPTS * CDIM];   // holds  y_hat  (fp16)
__device__ float     g_partial[256];
__device__ unsigned  g_done;

// ---------------- PTX helpers (plain sm_80+ instructions only) -------------
__device__ __forceinline__ uint32_t smem_u32(const void* p) {
    uint32_t a;
    asm("{ .reg .u64 t; cvta.to.shared.u64 t, %1; cvt.u32.u64 %0, t; }" : "=r"(a) : "l"(p));
    return a;
}
__device__ __forceinline__ void ldmatrix_x4(uint32_t& r0, uint32_t& r1,
                                            uint32_t& r2, uint32_t& r3, uint32_t addr) {
    asm volatile("ldmatrix.sync.aligned.m8n8.x4.shared.b16 {%0,%1,%2,%3}, [%4];"
                 : "=r"(r0), "=r"(r1), "=r"(r2), "=r"(r3) : "r"(addr));
}
// fp16 inputs, fp16 accumulators (2 regs)
__device__ __forceinline__ void mma16816_f16(uint32_t* d, const uint32_t* a,
                                             uint32_t b0, uint32_t b1) {
    asm volatile("mma.sync.aligned.m16n8k16.row.col.f16.f16.f16.f16 "
                 "{%0,%1}, {%2,%3,%4,%5}, {%6,%7}, {%0,%1};"
                 : "+r"(d[0]), "+r"(d[1])
                 : "r"(a[0]), "r"(a[1]), "r"(a[2]), "r"(a[3]), "r"(b0), "r"(b1));
}
#define CP_ASYNC16(dst, src) \
    asm volatile("cp.async.cg.shared.global [%0], [%1], 16;" :: "r"(dst), "l"(src))
#define CP_COMMIT() asm volatile("cp.async.commit_group;" ::: "memory")
#define CP_WAIT0()  asm volatile("cp.async.wait_group 0;" ::: "memory")

// ---------------- kernel 1: fused convert(fp16) + norm + min-init -----------
// set1 stored as -2 * rn(x) (exact scaling); norm1 = ||rn(x)||^2 = 0.25*sum(stored^2)
__global__ void prep_kernel(const float* __restrict__ s1, const float* __restrict__ s2) {
    if (blockIdx.x == 0 && threadIdx.x == 0) g_done = 0;
    const int total1 = BATCH * NPTS;
    int row = blockIdx.x * 32 + (threadIdx.x >> 3);
    int sub = threadIdx.x & 7;
    bool isA = row < total1;
    const float* src;
    __half* dst;
    int j;
    if (isA) { src = s1; dst = g_h1; j = row; }
    else     { src = s2; dst = g_h2; j = row - total1; }
    const float mul = isA ? -2.0f : 1.0f;
    const float* rp = src + (size_t)j * CDIM + sub * 16;
    __half* wp = dst + (size_t)j * CDIM + sub * 16;

    float s = 0.f;
#pragma unroll
    for (int h = 0; h < 2; h++) {
        float4 a = *reinterpret_cast<const float4*>(rp + h * 8);
        float4 b = *reinterpret_cast<const float4*>(rp + h * 8 + 4);
        __half2 p0 = __floats2half2_rn(mul * a.x, mul * a.y);
        __half2 p1 = __floats2half2_rn(mul * a.z, mul * a.w);
        __half2 p2 = __floats2half2_rn(mul * b.x, mul * b.y);
        __half2 p3 = __floats2half2_rn(mul * b.z, mul * b.w);
        uint4 o;
        o.x = *reinterpret_cast<unsigned*>(&p0);
        o.y = *reinterpret_cast<unsigned*>(&p1);
        o.z = *reinterpret_cast<unsigned*>(&p2);
        o.w = *reinterpret_cast<unsigned*>(&p3);
        *reinterpret_cast<uint4*>(wp + h * 8) = o;
        float2 f0 = __half22float2(p0);
        float2 f1 = __half22float2(p1);
        float2 f2 = __half22float2(p2);
        float2 f3 = __half22float2(p3);
        s += f0.x * f0.x + f0.y * f0.y + f1.x * f1.x + f1.y * f1.y;
        s += f2.x * f2.x + f2.y * f2.y + f3.x * f3.x + f3.y * f3.y;
    }
    s += __shfl_down_sync(0xffffffffu, s, 4, 8);
    s += __shfl_down_sync(0xffffffffu, s, 2, 8);
    s += __shfl_down_sync(0xffffffffu, s, 1, 8);
    if (sub == 0) {
        if (isA) { g_norm1[j] = 0.25f * s; g_rowmin[j] = INF_BITS; }
        else     { g_norm2[j] = s;         g_colmin[j] = INF_BITS; }
    }
}

// ---------------- kernel 2: strip-persistent mma GEMM + min epilogue --------
static constexpr int SMEM_A_OFF  = 0;          // 32 KB (A resident for strip)
static constexpr int SMEM_B0_OFF = 32768;      // 32 KB
static constexpr int SMEM_B1_OFF = 65536;      // 32 KB
static constexpr int SMEM_N1     = 98304;      // 128 f32
static constexpr int SMEM_N2     = 98816;      // 128 f32
static constexpr int SMEM_RMIN   = 99328;      // 128 u32
static constexpr int SMEM_CMIN   = 99840;      // 128 u32
static constexpr int SMEM_TOTAL  = 100352;

__global__ __launch_bounds__(256, 2)
void chamfer_mma() {
    extern __shared__ char smem[];
    const uint32_t sb = smem_u32(smem);
    const int tid  = threadIdx.x;
    const int wid  = tid >> 5;
    const int lane = tid & 31;
    const int wr   = wid >> 2;        // 0..1 (64 rows)
    const int wc   = wid & 3;         // 0..3 (32 cols)
    const int brow  = blockIdx.y * TILE;
    const int bcol0 = blockIdx.x * (TILE * STRIP);
    const int b     = blockIdx.z;

    float*    n1s    = reinterpret_cast<float*>(smem + SMEM_N1);
    float*    n2s    = reinterpret_cast<float*>(smem + SMEM_N2);
    unsigned* rmin_s = reinterpret_cast<unsigned*>(smem + SMEM_RMIN);
    unsigned* cmin_s = reinterpret_cast<unsigned*>(smem + SMEM_CMIN);

    const __half* Ag  = g_h1 + ((size_t)b * NPTS + brow) * CDIM;
    const __half* Bg0 = g_h2 + ((size_t)b * MPTS + bcol0) * CDIM;

    // ---- prologue: async-load A tile + B tile 0 (one commit group) ----
#pragma unroll
    for (int p = 0; p < 8; p++) {
        int c = p * 256 + tid;
        int row = c >> 4, col16 = c & 15;
        uint32_t so = row * 256 + ((col16 ^ (row & 7)) << 4);
        CP_ASYNC16(sb + SMEM_A_OFF + so,  Ag  + row * CDIM + col16 * 8);
    }
#pragma unroll
    for (int p = 0; p < 8; p++) {
        int c = p * 256 + tid;
        int row = c >> 4, col16 = c & 15;
        uint32_t so = row * 256 + ((col16 ^ (row & 7)) << 4);
        CP_ASYNC16(sb + SMEM_B0_OFF + so, Bg0 + row * CDIM + col16 * 8);
    }
    CP_COMMIT();
    if (tid < TILE) {
        n1s[tid] = g_norm1[b * NPTS + brow + tid];
        rmin_s[tid] = INF_BITS;
    }

    // thread geometry inside warp
    const int m  = lane >> 3;
    const int li = lane & 7;
    const int ksel = m >> 1;
    const int q = lane >> 2;
    const int s = lane & 3;
    const float INF = __uint_as_float(INF_BITS);

    uint32_t a_base[4];
#pragma unroll
    for (int mi = 0; mi < 4; mi++)
        a_base[mi] = sb + SMEM_A_OFF + (wr * 64 + mi * 16 + (m & 1) * 8 + li) * 256;

    float n1r[4][2];
    float rowm[4][2];
#pragma unroll
    for (int mi = 0; mi < 4; mi++) { rowm[mi][0] = INF; rowm[mi][1] = INF; }

    for (int it = 0; it < STRIP; it++) {
        CP_WAIT0();
        __syncthreads();   // orders: prev epilogue smem atomics, B-buffer fill

        // pipelined flush of PREVIOUS tile's column mins + reinit (same-thread RMW)
        if (tid < TILE) {
            if (it > 0)
                atomicMin(&g_colmin[b * MPTS + bcol0 + (it - 1) * TILE + tid], cmin_s[tid]);
            cmin_s[tid] = INF_BITS;
            n2s[tid] = g_norm2[b * MPTS + bcol0 + it * TILE + tid];
        }

        // prefetch next B tile into the other buffer (overlaps mainloop)
        if (it + 1 < STRIP) {
            const __half* Bn = Bg0 + (size_t)(it + 1) * TILE * CDIM;
            uint32_t dstb = sb + ((it + 1) & 1 ? SMEM_B1_OFF : SMEM_B0_OFF);
#pragma unroll
            for (int p = 0; p < 8; p++) {
                int c = p * 256 + tid;
                int row = c >> 4, col16 = c & 15;
                uint32_t so = row * 256 + ((col16 ^ (row & 7)) << 4);
                CP_ASYNC16(dstb + so, Bn + row * CDIM + col16 * 8);
            }
            CP_COMMIT();
        }
        if (it == 0) {
#pragma unroll
            for (int mi = 0; mi < 4; mi++) {
                n1r[mi][0] = n1s[wr * 64 + mi * 16 + q];
                n1r[mi][1] = n1s[wr * 64 + mi * 16 + q + 8];
            }
        }

        // ---- mainloop on buffer it&1 ----
        const uint32_t sbB = sb + ((it & 1) ? SMEM_B1_OFF : SMEM_B0_OFF);
        uint32_t b_base[2];
#pragma unroll
        for (int nj2 = 0; nj2 < 2; nj2++)
            b_base[nj2] = sbB + (wc * 32 + nj2 * 16 + (m & 1) * 8 + li) * 256;

        uint32_t acc[4][4][2];   // fp16x2 accumulators: [0]=rows q, [1]=rows q+8
#pragma unroll
        for (int mi = 0; mi < 4; mi++)
#pragma unroll
            for (int nj = 0; nj < 4; nj++) { acc[mi][nj][0] = 0u; acc[mi][nj][1] = 0u; }

#pragma unroll
        for (int kk = 0; kk < 8; kk++) {
            const uint32_t xoff = (uint32_t)(((kk * 2 + ksel) ^ li) << 4);
            uint32_t af[4][4], bf[2][4];
#pragma unroll
            for (int mi = 0; mi < 4; mi++)
                ldmatrix_x4(af[mi][0], af[mi][1], af[mi][2], af[mi][3], a_base[mi] + xoff);
#pragma unroll
            for (int nj2 = 0; nj2 < 2; nj2++)
                ldmatrix_x4(bf[nj2][0], bf[nj2][1], bf[nj2][2], bf[nj2][3], b_base[nj2] + xoff);
#pragma unroll
            for (int mi = 0; mi < 4; mi++)
#pragma unroll
                for (int nj = 0; nj < 4; nj++)
                    mma16816_f16(acc[mi][nj], af[mi], bf[nj >> 1][nj & 1], bf[nj >> 1][2 + (nj & 1)]);
        }
        __syncthreads();   // mainloop done; n2s/cmin ready for epilogue

        // ---- epilogue: acc = -2*dot (fp16x2). rowm folds (n2+t); colm folds (n1+t) ----
        float n2c[4][2];
#pragma unroll
        for (int nj = 0; nj < 4; nj++) {
            n2c[nj][0] = n2s[wc * 32 + nj * 8 + 2 * s];
            n2c[nj][1] = n2s[wc * 32 + nj * 8 + 2 * s + 1];
        }
        float colm[4][2];
#pragma unroll
        for (int nj = 0; nj < 4; nj++) { colm[nj][0] = INF; colm[nj][1] = INF; }

#pragma unroll
        for (int mi = 0; mi < 4; mi++) {
#pragma unroll
            for (int nj = 0; nj < 4; nj++) {
                float2 lo = __half22float2(*reinterpret_cast<__half2*>(&acc[mi][nj][0]));
                float2 hi = __half22float2(*reinterpret_cast<__half2*>(&acc[mi][nj][1]));
                // lo.x=(q,2s) lo.y=(q,2s+1) hi.x=(q+8,2s) hi.y=(q+8,2s+1)
                rowm[mi][0] = fminf(rowm[mi][0], lo.x + n2c[nj][0]);
                rowm[mi][0] = fminf(rowm[mi][0], lo.y + n2c[nj][1]);
                rowm[mi][1] = fminf(rowm[mi][1], hi.x + n2c[nj][0]);
                rowm[mi][1] = fminf(rowm[mi][1], hi.y + n2c[nj][1]);
                colm[nj][0] = fminf(colm[nj][0], lo.x + n1r[mi][0]);
                colm[nj][1] = fminf(colm[nj][1], lo.y + n1r[mi][0]);
                colm[nj][0] = fminf(colm[nj][0], hi.x + n1r[mi][1]);
                colm[nj][1] = fminf(colm[nj][1], hi.y + n1r[mi][1]);
            }
        }
        // column reduce across the 8 q-lanes, add n2, clamp, smem atomic
#pragma unroll
        for (int nj = 0; nj < 4; nj++) {
#pragma unroll
            for (int h = 0; h < 2; h++) {
                float v = colm[nj][h];
                v = fminf(v, __shfl_xor_sync(0xffffffffu, v, 4));
                v = fminf(v, __shfl_xor_sync(0xffffffffu, v, 8));
                v = fminf(v, __shfl_xor_sync(0xffffffffu, v, 16));
                if (q == 0) {
                    float d2 = fmaxf(v + n2c[nj][h], 0.0f);
                    atomicMin(&cmin_s[wc * 32 + nj * 8 + 2 * s + h], __float_as_uint(d2));
                }
            }
        }
        // NO trailing sync: next iteration's loop-head sync orders the flush.
    }

    __syncthreads();   // final tile's epilogue atomics complete
    if (tid < TILE)
        atomicMin(&g_colmin[b * MPTS + bcol0 + (STRIP - 1) * TILE + tid], cmin_s[tid]);

    // ---- strip end: row reduce across the 4 s-lanes, add n1, clamp ----
#pragma unroll
    for (int mi = 0; mi < 4; mi++) {
#pragma unroll
        for (int h = 0; h < 2; h++) {
            float v = rowm[mi][h];
            v = fminf(v, __shfl_xor_sync(0xffffffffu, v, 1));
            v = fminf(v, __shfl_xor_sync(0xffffffffu, v, 2));
            if (s == 0) {
                float d2 = fmaxf(v + n1r[mi][h], 0.0f);
                atomicMin(&rmin_s[wr * 64 + mi * 16 + q + h * 8], __float_as_uint(d2));
            }
        }
    }
    __syncthreads();
    if (tid < TILE)
        atomicMin(&g_rowmin[b * NPTS + brow + tid], rmin_s[tid]);
}

// ---------------- kernel 3: fused deterministic weighted reduction ----------
// 256 blocks x 256 threads, exactly one element per thread (65536 total).
__global__ void reduce_all(const float* __restrict__ w1,
                           const float* __restrict__ w2,
                           float* __restrict__ out) {
    __shared__ float red[256];
    __shared__ unsigned slast;
    const int t = threadIdx.x;
    const int bid = blockIdx.x;            // 0..255
    const int total1 = BATCH * NPTS;       // 32768
    const int idx = bid * 256 + t;         // 0 .. 65535
    float sum;
    if (idx < total1)
        sum = w1[idx] * sqrtf(__uint_as_float(g_rowmin[idx]));
    else {
        int j = idx - total1;              // 0 .. 32767
        sum = w2[j] * sqrtf(__uint_as_float(g_colmin[j]));
    }
    red[t] = sum;
    __syncthreads();
    for (int o = 128; o > 0; o >>= 1) {
        if (t < o) red[t] += red[t + o];
        __syncthreads();
    }
    if (t == 0) {
        g_partial[bid] = red[0];
        __threadfence();
        unsigned prev = atomicAdd(&g_done, 1u);
        slast = (prev == 255u) ? 1u : 0u;
    }
    __syncthreads();
    if (slast) {
        // last block: deterministic fixed-order final sum of 256 partials
        volatile float* gp = g_partial;
        red[t] = gp[t];
        __syncthreads();
        for (int o = 128; o > 0; o >>= 1) {
            if (t < o) red[t] += red[t + o];
            __syncthreads();
        }
        if (t == 0) out[0] = red[0] * 0.5f;
    }
}

// ---------------------------------------------------------------------------
extern "C" void kernel_launch(void* const* d_in, const int* in_sizes, int n_in,
                              void* d_out, int out_size) {
    const float* set1 = (const float*)d_in[0];
    const float* set2 = (const float*)d_in[1];
    const float* w1   = (const float*)d_in[2];
    const float* w2   = (const float*)d_in[3];
    float* out = (float*)d_out;
    (void)in_sizes; (void)n_in; (void)out_size;

    static bool attr_done = false;
    if (!attr_done) {
        cudaFuncSetAttribute(chamfer_mma, cudaFuncAttributeMaxDynamicSharedMemorySize, SMEM_TOTAL);
        attr_done = true;
    }

    prep_kernel<<<2 * BATCH * NPTS / 32, 256>>>(set1, set2);
    dim3 grid(MPTS / (TILE * STRIP), NPTS / TILE, BATCH);
    chamfer_mma<<<grid, 256, SMEM_TOTAL>>>();
    reduce_all<<<256, 256>>>(w1, w2, out);
}

// round 16
// speedup vs baseline: 1.6861x; 1.0018x over previous
#include <cuda_runtime.h>
#include <cuda_fp16.h>
#include <cstdint>

#define BATCH 8
#define NPTS  4096
#define MPTS  4096
#define CDIM  128
#define TILE  128
#define STRIP 8          // B tiles per CTA (along columns)
#define INF_BITS 0x7F800000u

// ---------------- device scratch (no allocation allowed) -------------------
__device__ unsigned  g_rowmin[BATCH * NPTS];
__device__ unsigned  g_colmin[BATCH * MPTS];
__device__ float     g_norm1[BATCH * NPTS];
__device__ float     g_norm2[BATCH * MPTS];
__device__ __half    g_h1[BATCH * NPTS * CDIM];   // holds -2*x_hat (fp16)
__device__ __half    g_h2[BATCH * MPTS * CDIM];   // holds  y_hat  (fp16)
__device__ float     g_partial[256];
__device__ unsigned  g_done;

// ---------------- PTX helpers (plain sm_80+ instructions only) -------------
__device__ __forceinline__ uint32_t smem_u32(const void* p) {
    uint32_t a;
    asm("{ .reg .u64 t; cvta.to.shared.u64 t, %1; cvt.u32.u64 %0, t; }" : "=r"(a) : "l"(p));
    return a;
}
__device__ __forceinline__ void ldmatrix_x4(uint32_t& r0, uint32_t& r1,
                                            uint32_t& r2, uint32_t& r3, uint32_t addr) {
    asm volatile("ldmatrix.sync.aligned.m8n8.x4.shared.b16 {%0,%1,%2,%3}, [%4];"
                 : "=r"(r0), "=r"(r1), "=r"(r2), "=r"(r3) : "r"(addr));
}
// fp16 inputs, fp16 accumulators (2 regs)
__device__ __forceinline__ void mma16816_f16(uint32_t* d, const uint32_t* a,
                                             uint32_t b0, uint32_t b1) {
    asm volatile("mma.sync.aligned.m16n8k16.row.col.f16.f16.f16.f16 "
                 "{%0,%1}, {%2,%3,%4,%5}, {%6,%7}, {%0,%1};"
                 : "+r"(d[0]), "+r"(d[1])
                 : "r"(a[0]), "r"(a[1]), "r"(a[2]), "r"(a[3]), "r"(b0), "r"(b1));
}
#define CP_ASYNC16(dst, src) \
    asm volatile("cp.async.cg.shared.global [%0], [%1], 16;" :: "r"(dst), "l"(src))
#define CP_COMMIT() asm volatile("cp.async.commit_group;" ::: "memory")
#define CP_WAIT0()  asm volatile("cp.async.wait_group 0;" ::: "memory")

// ---------------- kernel 1: fused convert(fp16) + norm + min-init -----------
// set1 stored as -2 * rn(x) (exact scaling); norm1 = ||rn(x)||^2 = 0.25*sum(stored^2)
__global__ void prep_kernel(const float* __restrict__ s1, const float* __restrict__ s2) {
    if (blockIdx.x == 0 && threadIdx.x == 0) g_done = 0;
    const int total1 = BATCH * NPTS;
    int row = blockIdx.x * 32 + (threadIdx.x >> 3);
    int sub = threadIdx.x & 7;
    bool isA = row < total1;
    const float* src;
    __half* dst;
    int j;
    if (isA) { src = s1; dst = g_h1; j = row; }
    else     { src = s2; dst = g_h2; j = row - total1; }
    const float mul = isA ? -2.0f : 1.0f;
    const float* rp = src + (size_t)j * CDIM + sub * 16;
    __half* wp = dst + (size_t)j * CDIM + sub * 16;

    float s = 0.f;
#pragma unroll
    for (int h = 0; h < 2; h++) {
        float4 a = *reinterpret_cast<const float4*>(rp + h * 8);
        float4 b = *reinterpret_cast<const float4*>(rp + h * 8 + 4);
        __half2 p0 = __floats2half2_rn(mul * a.x, mul * a.y);
        __half2 p1 = __floats2half2_rn(mul * a.z, mul * a.w);
        __half2 p2 = __floats2half2_rn(mul * b.x, mul * b.y);
        __half2 p3 = __floats2half2_rn(mul * b.z, mul * b.w);
        uint4 o;
        o.x = *reinterpret_cast<unsigned*>(&p0);
        o.y = *reinterpret_cast<unsigned*>(&p1);
        o.z = *reinterpret_cast<unsigned*>(&p2);
        o.w = *reinterpret_cast<unsigned*>(&p3);
        *reinterpret_cast<uint4*>(wp + h * 8) = o;
        float2 f0 = __half22float2(p0);
        float2 f1 = __half22float2(p1);
        float2 f2 = __half22float2(p2);
        float2 f3 = __half22float2(p3);
        s += f0.x * f0.x + f0.y * f0.y + f1.x * f1.x + f1.y * f1.y;
        s += f2.x * f2.x + f2.y * f2.y + f3.x * f3.x + f3.y * f3.y;
    }
    s += __shfl_down_sync(0xffffffffu, s, 4, 8);
    s += __shfl_down_sync(0xffffffffu, s, 2, 8);
    s += __shfl_down_sync(0xffffffffu, s, 1, 8);
    if (sub == 0) {
        if (isA) { g_norm1[j] = 0.25f * s; g_rowmin[j] = INF_BITS; }
        else     { g_norm2[j] = s;         g_colmin[j] = INF_BITS; }
    }
}

// ---------------- kernel 2: strip-persistent mma GEMM + min epilogue --------
static constexpr int SMEM_A_OFF  = 0;          // 32 KB (A resident for strip)
static constexpr int SMEM_B0_OFF = 32768;      // 32 KB
static constexpr int SMEM_B1_OFF = 65536;      // 32 KB
static constexpr int SMEM_N1     = 98304;      // 128 f32
static constexpr int SMEM_N2     = 98816;      // 128 f32
static constexpr int SMEM_RMIN   = 99328;      // 128 u32
static constexpr int SMEM_CMIN   = 99840;      // 128 u32
static constexpr int SMEM_TOTAL  = 100352;

__global__ __launch_bounds__(256, 2)
void chamfer_mma() {
    extern __shared__ char smem[];
    const uint32_t sb = smem_u32(smem);
    const int tid  = threadIdx.x;
    const int wid  = tid >> 5;
    const int lane = tid & 31;
    const int wr   = wid >> 2;        // 0..1 (64 rows)
    const int wc   = wid & 3;         // 0..3 (32 cols)
    const int brow  = blockIdx.y * TILE;
    const int bcol0 = blockIdx.x * (TILE * STRIP);
    const int b     = blockIdx.z;

    float*    n1s    = reinterpret_cast<float*>(smem + SMEM_N1);
    float*    n2s    = reinterpret_cast<float*>(smem + SMEM_N2);
    unsigned* rmin_s = reinterpret_cast<unsigned*>(smem + SMEM_RMIN);
    unsigned* cmin_s = reinterpret_cast<unsigned*>(smem + SMEM_CMIN);

    const __half* Ag  = g_h1 + ((size_t)b * NPTS + brow) * CDIM;
    const __half* Bg0 = g_h2 + ((size_t)b * MPTS + bcol0) * CDIM;

    // ---- prologue: async-load A tile + B tile 0 (one commit group) ----
#pragma unroll
    for (int p = 0; p < 8; p++) {
        int c = p * 256 + tid;
        int row = c >> 4, col16 = c & 15;
        uint32_t so = row * 256 + ((col16 ^ (row & 7)) << 4);
        CP_ASYNC16(sb + SMEM_A_OFF + so,  Ag  + row * CDIM + col16 * 8);
    }
#pragma unroll
    for (int p = 0; p < 8; p++) {
        int c = p * 256 + tid;
        int row = c >> 4, col16 = c & 15;
        uint32_t so = row * 256 + ((col16 ^ (row & 7)) << 4);
        CP_ASYNC16(sb + SMEM_B0_OFF + so, Bg0 + row * CDIM + col16 * 8);
    }
    CP_COMMIT();
    if (tid < TILE) {
        n1s[tid] = g_norm1[b * NPTS + brow + tid];
        rmin_s[tid] = INF_BITS;
    }

    // thread geometry inside warp
    const int m  = lane >> 3;
    const int li = lane & 7;
    const int ksel = m >> 1;
    const int q = lane >> 2;
    const int s = lane & 3;
    const float INF = __uint_as_float(INF_BITS);

    uint32_t a_base[4];
#pragma unroll
    for (int mi = 0; mi < 4; mi++)
        a_base[mi] = sb + SMEM_A_OFF + (wr * 64 + mi * 16 + (m & 1) * 8 + li) * 256;

    float n1r[4][2];
    float rowm[4][2];
#pragma unroll
    for (int mi = 0; mi < 4; mi++) { rowm[mi][0] = INF; rowm[mi][1] = INF; }

    for (int it = 0; it < STRIP; it++) {
        CP_WAIT0();
        __syncthreads();   // orders: prev epilogue smem atomics, B-buffer fill

        // pipelined flush of PREVIOUS tile's column mins + reinit (same-thread RMW)
        if (tid < TILE) {
            if (it > 0)
                atomicMin(&g_colmin[b * MPTS + bcol0 + (it - 1) * TILE + tid], cmin_s[tid]);
            cmin_s[tid] = INF_BITS;
            n2s[tid] = g_norm2[b * MPTS + bcol0 + it * TILE + tid];
        }

        // prefetch next B tile into the other buffer (overlaps mainloop)
        if (it + 1 < STRIP) {
            const __half* Bn = Bg0 + (size_t)(it + 1) * TILE * CDIM;
            uint32_t dstb = sb + ((it + 1) & 1 ? SMEM_B1_OFF : SMEM_B0_OFF);
#pragma unroll
            for (int p = 0; p < 8; p++) {
                int c = p * 256 + tid;
                int row = c >> 4, col16 = c & 15;
                uint32_t so = row * 256 + ((col16 ^ (row & 7)) << 4);
                CP_ASYNC16(dstb + so, Bn + row * CDIM + col16 * 8);
            }
            CP_COMMIT();
        }
        if (it == 0) {
#pragma unroll
            for (int mi = 0; mi < 4; mi++) {
                n1r[mi][0] = n1s[wr * 64 + mi * 16 + q];
                n1r[mi][1] = n1s[wr * 64 + mi * 16 + q + 8];
            }
        }

        // ---- mainloop on buffer it&1 ----
        const uint32_t sbB = sb + ((it & 1) ? SMEM_B1_OFF : SMEM_B0_OFF);
        uint32_t b_base[2];
#pragma unroll
        for (int nj2 = 0; nj2 < 2; nj2++)
            b_base[nj2] = sbB + (wc * 32 + nj2 * 16 + (m & 1) * 8 + li) * 256;

        uint32_t acc[4][4][2];   // fp16x2 accumulators: [0]=rows q, [1]=rows q+8
#pragma unroll
        for (int mi = 0; mi < 4; mi++)
#pragma unroll
            for (int nj = 0; nj < 4; nj++) { acc[mi][nj][0] = 0u; acc[mi][nj][1] = 0u; }

#pragma unroll
        for (int kk = 0; kk < 8; kk++) {
            const uint32_t xoff = (uint32_t)(((kk * 2 + ksel) ^ li) << 4);
            uint32_t af[4][4], bf[2][4];
#pragma unroll
            for (int mi = 0; mi < 4; mi++)
                ldmatrix_x4(af[mi][0], af[mi][1], af[mi][2], af[mi][3], a_base[mi] + xoff);
#pragma unroll
            for (int nj2 = 0; nj2 < 2; nj2++)
                ldmatrix_x4(bf[nj2][0], bf[nj2][1], bf[nj2][2], bf[nj2][3], b_base[nj2] + xoff);
#pragma unroll
            for (int mi = 0; mi < 4; mi++)
#pragma unroll
                for (int nj = 0; nj < 4; nj++)
                    mma16816_f16(acc[mi][nj], af[mi], bf[nj >> 1][nj & 1], bf[nj >> 1][2 + (nj & 1)]);
        }
        __syncthreads();   // mainloop done; n2s/cmin ready for epilogue

        // ---- epilogue: acc = -2*dot (fp16x2). rowm folds (n2+t); colm folds (n1+t) ----
        float n2c[4][2];
#pragma unroll
        for (int nj = 0; nj < 4; nj++) {
            n2c[nj][0] = n2s[wc * 32 + nj * 8 + 2 * s];
            n2c[nj][1] = n2s[wc * 32 + nj * 8 + 2 * s + 1];
        }
        float colm[4][2];
#pragma unroll
        for (int nj = 0; nj < 4; nj++) { colm[nj][0] = INF; colm[nj][1] = INF; }

#pragma unroll
        for (int mi = 0; mi < 4; mi++) {
#pragma unroll
            for (int nj = 0; nj < 4; nj++) {
                float2 lo = __half22float2(*reinterpret_cast<__half2*>(&acc[mi][nj][0]));
                float2 hi = __half22float2(*reinterpret_cast<__half2*>(&acc[mi][nj][1]));
                // lo.x=(q,2s) lo.y=(q,2s+1) hi.x=(q+8,2s) hi.y=(q+8,2s+1)
                rowm[mi][0] = fminf(rowm[mi][0], lo.x + n2c[nj][0]);
                rowm[mi][0] = fminf(rowm[mi][0], lo.y + n2c[nj][1]);
                rowm[mi][1] = fminf(rowm[mi][1], hi.x + n2c[nj][0]);
                rowm[mi][1] = fminf(rowm[mi][1], hi.y + n2c[nj][1]);
                colm[nj][0] = fminf(colm[nj][0], lo.x + n1r[mi][0]);
                colm[nj][1] = fminf(colm[nj][1], lo.y + n1r[mi][0]);
                colm[nj][0] = fminf(colm[nj][0], hi.x + n1r[mi][1]);
                colm[nj][1] = fminf(colm[nj][1], hi.y + n1r[mi][1]);
            }
        }
        // column reduce across the 8 q-lanes, add n2, clamp, smem atomic
#pragma unroll
        for (int nj = 0; nj < 4; nj++) {
#pragma unroll
            for (int h = 0; h < 2; h++) {
                float v = colm[nj][h];
                v = fminf(v, __shfl_xor_sync(0xffffffffu, v, 4));
                v = fminf(v, __shfl_xor_sync(0xffffffffu, v, 8));
                v = fminf(v, __shfl_xor_sync(0xffffffffu, v, 16));
                if (q == 0) {
                    float d2 = fmaxf(v + n2c[nj][h], 0.0f);
                    atomicMin(&cmin_s[wc * 32 + nj * 8 + 2 * s + h], __float_as_uint(d2));
                }
            }
        }
        // NO trailing sync: next iteration's loop-head sync orders the flush.
    }

    __syncthreads();   // final tile's epilogue atomics complete
    if (tid < TILE)
        atomicMin(&g_colmin[b * MPTS + bcol0 + (STRIP - 1) * TILE + tid], cmin_s[tid]);

    // ---- strip end: row reduce across the 4 s-lanes, add n1, clamp ----
#pragma unroll
    for (int mi = 0; mi < 4; mi++) {
#pragma unroll
        for (int h = 0; h < 2; h++) {
            float v = rowm[mi][h];
            v = fminf(v, __shfl_xor_sync(0xffffffffu, v, 1));
            v = fminf(v, __shfl_xor_sync(0xffffffffu, v, 2));
            if (s == 0) {
                float d2 = fmaxf(v + n1r[mi][h], 0.0f);
                atomicMin(&rmin_s[wr * 64 + mi * 16 + q + h * 8], __float_as_uint(d2));
            }
        }
    }
    __syncthreads();
    if (tid < TILE)
        atomicMin(&g_rowmin[b * NPTS + brow + tid], rmin_s[tid]);
}

// ---------------- kernel 3: fused deterministic weighted reduction ----------
// 256 blocks x 256 threads, exactly one element per thread (65536 total).
__global__ void reduce_all(const float* __restrict__ w1,
                           const float* __restrict__ w2,
                           float* __restrict__ out) {
    __shared__ float red[256];
    __shared__ unsigned slast;
    const int t = threadIdx.x;
    const int bid = blockIdx.x;            // 0..255
    const int total1 = BATCH * NPTS;       // 32768
    const int idx = bid * 256 + t;         // 0 .. 65535
    float sum;
    if (idx < total1)
        sum = w1[idx] * sqrtf(__uint_as_float(g_rowmin[idx]));
    else {
        int j = idx - total1;              // 0 .. 32767
        sum = w2[j] * sqrtf(__uint_as_float(g_colmin[j]));
    }
    red[t] = sum;
    __syncthreads();
    for (int o = 128; o > 0; o >>= 1) {
        if (t < o) red[t] += red[t + o];
        __syncthreads();
    }
    if (t == 0) {
        g_partial[bid] = red[0];
        __threadfence();
        unsigned prev = atomicAdd(&g_done, 1u);
        slast = (prev == 255u) ? 1u : 0u;
    }
    __syncthreads();
    if (slast) {
        // last block: deterministic fixed-order final sum of 256 partials
        volatile float* gp = g_partial;
        red[t] = gp[t];
        __syncthreads();
        for (int o = 128; o > 0; o >>= 1) {
            if (t < o) red[t] += red[t + o];
            __syncthreads();
        }
        if (t == 0) out[0] = red[0] * 0.5f;
    }
}

// ---------------------------------------------------------------------------
extern "C" void kernel_launch(void* const* d_in, const int* in_sizes, int n_in,
                              void* d_out, int out_size) {
    const float* set1 = (const float*)d_in[0];
    const float* set2 = (const float*)d_in[1];
    const float* w1   = (const float*)d_in[2];
    const float* w2   = (const float*)d_in[3];
    float* out = (float*)d_out;
    (void)in_sizes; (void)n_in; (void)out_size;

    static bool attr_done = false;
    if (!attr_done) {
        cudaFuncSetAttribute(chamfer_mma, cudaFuncAttributeMaxDynamicSharedMemorySize, SMEM_TOTAL);
        attr_done = true;
    }

    prep_kernel<<<2 * BATCH * NPTS / 32, 256>>>(set1, set2);
    dim3 grid(MPTS / (TILE * STRIP), NPTS / TILE, BATCH);
    chamfer_mma<<<grid, 256, SMEM_TOTAL>>>();
    reduce_all<<<256, 256>>>(w1, w2, out);
}